// round 1
// baseline (speedup 1.0000x reference)
#include <cuda_runtime.h>

#define NQ   1024
#define DIM  512
#define KQ   65536
#define KD   (KQ * DIM)        /* 33554432 */
#define NCLS 1000
#define TOPK 200

// 256 MB sim scratch + correct-count accumulator (device globals: allocation-guard safe)
__device__ float g_sim[(size_t)NQ * KQ];
__device__ int   g_correct;

// ---------------------------------------------------------------------------
// Kernel 1: circular-queue update copy + label copy + ptr + reset accumulator
// out layout: [0]=accuracy, [1..1+KD)=queue_features, [1+KD..1+KD+KQ)=labels(float), [last]=ptr
// ---------------------------------------------------------------------------
__global__ void copy_update_kernel(const float* __restrict__ feats,
                                   const float* __restrict__ qf,
                                   const int*   __restrict__ labels,
                                   const int*   __restrict__ qlabels,
                                   const int*   __restrict__ qptr,
                                   float*       __restrict__ out)
{
    long long e = (long long)blockIdx.x * blockDim.x + threadIdx.x;
    const int p = qptr[0];
    if (e < (long long)KD) {
        int row = (int)(e >> 9);       // D = 512
        int col = (int)(e & 511);
        unsigned rel = (unsigned)(row - p);
        float v = (rel < (unsigned)NQ) ? feats[rel * DIM + col] : qf[e];
        out[1 + e] = v;
    } else if (e < (long long)KD + KQ) {
        int i = (int)(e - KD);
        unsigned rel = (unsigned)(i - p);
        int v = (rel < (unsigned)NQ) ? labels[rel] : qlabels[i];
        out[1 + e] = (float)v;
    } else if (e == (long long)KD + KQ) {
        out[1 + e] = (float)((p + NQ) % KQ);
        g_correct = 0;
    }
}

// ---------------------------------------------------------------------------
// Kernel 2: fp32 SGEMM  sim[n][k] = sum_d F[n][d] * Q[k][d]
// 128x128 CTA tile, BK=16, 256 threads, 8x8 per thread, double-buffered smem.
// Grid (8, 512): consecutive bids share the Q (B) tile -> L2 reuse.
// ---------------------------------------------------------------------------
__global__ __launch_bounds__(256) void gemm_kernel(const float* __restrict__ A,
                                                   const float* __restrict__ B)
{
    __shared__ float As[2][16][128];
    __shared__ float Bs[2][16][128];

    const int tid = threadIdx.x;
    const int tx = tid & 15;
    const int ty = tid >> 4;
    const int nBase = blockIdx.x * 128;
    const int kBase = blockIdx.y * 128;

    const int f0 = tid, f1 = tid + 256;
    const int r0 = f0 >> 2, c0 = (f0 & 3) << 2;
    const int r1 = f1 >> 2, c1 = (f1 & 3) << 2;

    const float* Ap = A + (size_t)nBase * DIM;
    const float* Bp = B + (size_t)kBase * DIM;

    float acc[8][8];
#pragma unroll
    for (int i = 0; i < 8; i++)
#pragma unroll
        for (int j = 0; j < 8; j++) acc[i][j] = 0.f;

    float4 a0 = *(const float4*)(Ap + r0 * DIM + c0);
    float4 a1 = *(const float4*)(Ap + r1 * DIM + c1);
    float4 b0 = *(const float4*)(Bp + r0 * DIM + c0);
    float4 b1 = *(const float4*)(Bp + r1 * DIM + c1);

#define STORE_TILE(bf) do { \
    As[bf][c0+0][r0]=a0.x; As[bf][c0+1][r0]=a0.y; As[bf][c0+2][r0]=a0.z; As[bf][c0+3][r0]=a0.w; \
    As[bf][c1+0][r1]=a1.x; As[bf][c1+1][r1]=a1.y; As[bf][c1+2][r1]=a1.z; As[bf][c1+3][r1]=a1.w; \
    Bs[bf][c0+0][r0]=b0.x; Bs[bf][c0+1][r0]=b0.y; Bs[bf][c0+2][r0]=b0.z; Bs[bf][c0+3][r0]=b0.w; \
    Bs[bf][c1+0][r1]=b1.x; Bs[bf][c1+1][r1]=b1.y; Bs[bf][c1+2][r1]=b1.z; Bs[bf][c1+3][r1]=b1.w; \
} while (0)

    STORE_TILE(0);
    __syncthreads();

    for (int kt = 0; kt < 32; kt++) {
        const int buf = kt & 1;
        if (kt < 31) {
            const int ko = (kt + 1) * 16;
            a0 = *(const float4*)(Ap + r0 * DIM + ko + c0);
            a1 = *(const float4*)(Ap + r1 * DIM + ko + c1);
            b0 = *(const float4*)(Bp + r0 * DIM + ko + c0);
            b1 = *(const float4*)(Bp + r1 * DIM + ko + c1);
        }
#pragma unroll
        for (int kk = 0; kk < 16; kk++) {
            float ra[8], rb[8];
            *(float4*)&ra[0] = *(const float4*)&As[buf][kk][ty * 4];
            *(float4*)&ra[4] = *(const float4*)&As[buf][kk][64 + ty * 4];
            *(float4*)&rb[0] = *(const float4*)&Bs[buf][kk][tx * 4];
            *(float4*)&rb[4] = *(const float4*)&Bs[buf][kk][64 + tx * 4];
#pragma unroll
            for (int i = 0; i < 8; i++)
#pragma unroll
                for (int j = 0; j < 8; j++)
                    acc[i][j] += ra[i] * rb[j];
        }
        if (kt < 31) {
            STORE_TILE(buf ^ 1);
            __syncthreads();
        }
    }
#undef STORE_TILE

#pragma unroll
    for (int i = 0; i < 8; i++) {
        int row = nBase + ((i >> 2) * 64) + ty * 4 + (i & 3);
        float* Cp = g_sim + (size_t)row * KQ + kBase;
        *(float4*)(Cp + tx * 4)      = make_float4(acc[i][0], acc[i][1], acc[i][2], acc[i][3]);
        *(float4*)(Cp + 64 + tx * 4) = make_float4(acc[i][4], acc[i][5], acc[i][6], acc[i][7]);
    }
}

// ---------------------------------------------------------------------------
// Kernel 3: per-row top-200 (histogram threshold + exact sort) + class voting
// One CTA (256 threads) per row.
// ---------------------------------------------------------------------------
__device__ __forceinline__ int sim_bin(float v)
{
    int b = (int)((v + 1.0f) * 2048.0f);
    return min(4095, max(0, b));
}

__global__ __launch_bounds__(256) void knn_select_kernel(const int* __restrict__ qlabels,
                                                         const int* __restrict__ labels)
{
    __shared__ unsigned hist[4096];
    __shared__ unsigned chunk[256];
    __shared__ float    cval[1024];
    __shared__ int      cidx[1024];
    __shared__ float    s_w[TOPK];
    __shared__ int      s_l[TOPK];
    __shared__ unsigned s_cnt;
    __shared__ int      s_tbin;

    const int tid = threadIdx.x;
    const int row = blockIdx.x;
    const float4* Sr4 = (const float4*)(g_sim + (size_t)row * KQ);

    for (int b = tid; b < 4096; b += 256) hist[b] = 0;
    if (tid == 0) s_cnt = 0;
    __syncthreads();

    // Pass 1: histogram over [-1, 1] with 4096 linear bins
    for (int s = 0; s < 64; s++) {
        float4 v = Sr4[tid + s * 256];
        atomicAdd(&hist[sim_bin(v.x)], 1u);
        atomicAdd(&hist[sim_bin(v.y)], 1u);
        atomicAdd(&hist[sim_bin(v.z)], 1u);
        atomicAdd(&hist[sim_bin(v.w)], 1u);
    }
    __syncthreads();

    // Per-thread chunk sums (16 bins each), then serial top-down scan for threshold bin
    {
        unsigned cs = 0;
        const int b0 = tid * 16;
#pragma unroll
        for (int b = 0; b < 16; b++) cs += hist[b0 + b];
        chunk[tid] = cs;
    }
    __syncthreads();

    if (tid == 0) {
        unsigned cum = 0;
        int tb = 0;
        for (int t = 255; t >= 0; t--) {
            if (cum + chunk[t] >= (unsigned)TOPK) {
                for (int b = t * 16 + 15;; b--) {
                    if (cum + hist[b] >= (unsigned)TOPK) { tb = b; break; }
                    cum += hist[b];
                }
                break;
            }
            cum += chunk[t];
        }
        s_tbin = tb;
    }
    __syncthreads();
    const int tb = s_tbin;

    // Pass 2: gather all candidates with bin >= threshold bin (count in [200, ~210])
    for (int s = 0; s < 64; s++) {
        const int base = tid + s * 256;
        float4 v = Sr4[base];
        float vv[4] = {v.x, v.y, v.z, v.w};
#pragma unroll
        for (int c = 0; c < 4; c++) {
            if (sim_bin(vv[c]) >= tb) {
                unsigned pos = atomicAdd(&s_cnt, 1u);
                if (pos < 1024u) { cval[pos] = vv[c]; cidx[pos] = base * 4 + c; }
            }
        }
    }
    __syncthreads();
    const int m = (int)min(s_cnt, 1024u);
    for (int i = tid; i < 1024; i += 256)
        if (i >= m) { cval[i] = -2.0f; cidx[i] = 0x7FFFFFFF; }
    __syncthreads();

    // Bitonic sort: descending by value, ascending by index on ties (== lax.top_k)
    for (int k = 2; k <= 1024; k <<= 1) {
        for (int j = k >> 1; j > 0; j >>= 1) {
            for (int t = tid; t < 1024; t += 256) {
                const int p = t ^ j;
                if (p > t) {
                    float v1 = cval[t], v2 = cval[p];
                    int i1 = cidx[t], i2 = cidx[p];
                    bool firstGreater = (v1 > v2) || (v1 == v2 && i1 < i2);
                    bool up = ((t & k) == 0);
                    if (up != firstGreater) {
                        cval[t] = v2; cval[p] = v1;
                        cidx[t] = i2; cidx[p] = i1;
                    }
                }
            }
            __syncthreads();
        }
    }

    // Weights + neighbor labels of the exact top-200
    if (tid < TOPK) {
        s_w[tid] = expf(cval[tid] * (1.0f / 0.07f));
        s_l[tid] = qlabels[cidx[tid]];
    }
    __syncthreads();

    // Per-class weighted vote (summed in rank order -> matches reference), argmax
    float best = -1.0f;
    int bc = 0;
#pragma unroll
    for (int rep = 0; rep < 4; rep++) {
        const int c = tid + rep * 256;
        if (c < NCLS) {
            float sc = 0.0f;
            for (int j = 0; j < TOPK; j++)
                if (s_l[j] == c) sc += s_w[j];
            if (sc > best) { best = sc; bc = c; }  // ascending c: strict > keeps lowest class on tie
        }
    }
    __syncthreads();  // cval/cidx reuse below
    cval[tid] = best; cidx[tid] = bc;
    __syncthreads();
    for (int off = 128; off > 0; off >>= 1) {
        if (tid < off) {
            float v2 = cval[tid + off]; int c2 = cidx[tid + off];
            if (v2 > cval[tid] || (v2 == cval[tid] && c2 < cidx[tid])) {
                cval[tid] = v2; cidx[tid] = c2;
            }
        }
        __syncthreads();
    }
    if (tid == 0 && cidx[0] == labels[row]) atomicAdd(&g_correct, 1);
}

// ---------------------------------------------------------------------------
// Kernel 4: finalize accuracy
// ---------------------------------------------------------------------------
__global__ void finalize_kernel(float* __restrict__ out)
{
    out[0] = (float)g_correct * (1.0f / 1024.0f);
}

// ---------------------------------------------------------------------------
extern "C" void kernel_launch(void* const* d_in, const int* in_sizes, int n_in,
                              void* d_out, int out_size)
{
    const float* feats   = (const float*)d_in[0];
    const float* qf      = (const float*)d_in[1];
    const int*   labels  = (const int*)d_in[2];
    const int*   qlabels = (const int*)d_in[3];
    const int*   qptr    = (const int*)d_in[4];
    float* out = (float*)d_out;

    const long long totalCopy = (long long)KD + KQ + 1;
    const int copyBlocks = (int)((totalCopy + 255) / 256);

    copy_update_kernel<<<copyBlocks, 256>>>(feats, qf, labels, qlabels, qptr, out);
    gemm_kernel<<<dim3(8, 512), 256>>>(feats, qf);
    knn_select_kernel<<<NQ, 256>>>(qlabels, labels);
    finalize_kernel<<<1, 1>>>(out);
}

// round 5
// speedup vs baseline: 1.5384x; 1.5384x over previous
#include <cuda_runtime.h>
#include <cuda_bf16.h>
#include <cstdint>

#define NQ   1024
#define DIM  512
#define KQ   65536
#define KD   (KQ * DIM)
#define NCLS 1000
#define TOPK 200
#define SPLITK 1536           /* 3 * DIM bf16-split K: [hi|lo|hi] */
#define BPK  1024             /* B' row width: [hi(512) | lo(512)] */
#define BK   32
#define NCHUNK 48             /* 1536 / 32 */

// Device scratch (allocation-guard-legal)
__device__ __align__(256) float          g_sim[(size_t)NQ * KQ];     // 256 MB
__device__ __align__(256) __nv_bfloat16  g_bf[(size_t)KQ * BPK];     // 128 MB  [hi|lo]
__device__ __align__(256) __nv_bfloat16  g_af[(size_t)NQ * SPLITK];  //   3 MB  [hi|lo|hi]
__device__ int g_correct;

// ---------------------------------------------------------------------------
// PTX helpers (all base-sm_103 legal: cp.async / ldmatrix / mma.sync)
// ---------------------------------------------------------------------------
__device__ __forceinline__ uint32_t smem_u32(const void* p) {
    uint32_t a;
    asm("{ .reg .u64 t; cvta.to.shared.u64 t, %1; cvt.u32.u64 %0, t; }" : "=r"(a) : "l"(p));
    return a;
}
#define CPASYNC(dst, src) \
    asm volatile("cp.async.cg.shared.global [%0], [%1], 16;" :: "r"(dst), "l"(src))
#define CP_COMMIT()  asm volatile("cp.async.commit_group;" ::: "memory")
#define CP_WAIT1()   asm volatile("cp.async.wait_group 1;" ::: "memory")

#define LDSM_X4(r0, r1, r2, r3, addr) \
    asm volatile("ldmatrix.sync.aligned.m8n8.x4.shared.b16 {%0,%1,%2,%3}, [%4];" \
                 : "=r"(r0), "=r"(r1), "=r"(r2), "=r"(r3) : "r"(addr))

#define MMA16816(c0, c1, c2, c3, a0, a1, a2, a3, b0, b1) \
    asm volatile("mma.sync.aligned.m16n8k16.row.col.f32.bf16.bf16.f32 " \
                 "{%0,%1,%2,%3}, {%4,%5,%6,%7}, {%8,%9}, {%0,%1,%2,%3};" \
                 : "+f"(c0), "+f"(c1), "+f"(c2), "+f"(c3) \
                 : "r"(a0), "r"(a1), "r"(a2), "r"(a3), "r"(b0), "r"(b1))

// ---------------------------------------------------------------------------
// Kernel 0a/0b: bf16 hi/lo split conversion
// ---------------------------------------------------------------------------
__global__ void conv_b_kernel(const float* __restrict__ qf)
{
    size_t i4 = (size_t)blockIdx.x * 256 + threadIdx.x;
    float4 v = ((const float4*)qf)[i4];
    int row = (int)(i4 >> 7);
    int c4  = (int)(i4 & 127);
    float f[4] = {v.x, v.y, v.z, v.w};
    __nv_bfloat16 h[4], l[4];
#pragma unroll
    for (int j = 0; j < 4; j++) {
        h[j] = __float2bfloat16(f[j]);
        l[j] = __float2bfloat16(f[j] - __bfloat162float(h[j]));
    }
    __nv_bfloat16* base = g_bf + (size_t)row * BPK + c4 * 4;
    *(uint2*)base         = *(uint2*)h;
    *(uint2*)(base + 512) = *(uint2*)l;
}

__global__ void conv_a_kernel(const float* __restrict__ feats)
{
    size_t i4 = (size_t)blockIdx.x * 256 + threadIdx.x;
    float4 v = ((const float4*)feats)[i4];
    int row = (int)(i4 >> 7);
    int c4  = (int)(i4 & 127);
    float f[4] = {v.x, v.y, v.z, v.w};
    __nv_bfloat16 h[4], l[4];
#pragma unroll
    for (int j = 0; j < 4; j++) {
        h[j] = __float2bfloat16(f[j]);
        l[j] = __float2bfloat16(f[j] - __bfloat162float(h[j]));
    }
    __nv_bfloat16* base = g_af + (size_t)row * SPLITK + c4 * 4;
    *(uint2*)base          = *(uint2*)h;   // seg0: A_hi
    *(uint2*)(base + 512)  = *(uint2*)l;   // seg1: A_lo
    *(uint2*)(base + 1024) = *(uint2*)h;   // seg2: A_hi
}

// ---------------------------------------------------------------------------
// Kernel 1: circular-queue update copy + label copy + ptr + reset accumulator
// ---------------------------------------------------------------------------
__global__ void copy_update_kernel(const float* __restrict__ feats,
                                   const float* __restrict__ qf,
                                   const int*   __restrict__ labels,
                                   const int*   __restrict__ qlabels,
                                   const int*   __restrict__ qptr,
                                   float*       __restrict__ out)
{
    long long e = (long long)blockIdx.x * blockDim.x + threadIdx.x;
    const int p = qptr[0];
    if (e < (long long)KD) {
        int row = (int)(e >> 9);
        int col = (int)(e & 511);
        unsigned rel = (unsigned)(row - p);
        float v = (rel < (unsigned)NQ) ? feats[rel * DIM + col] : qf[e];
        out[1 + e] = v;
    } else if (e < (long long)KD + KQ) {
        int i = (int)(e - KD);
        unsigned rel = (unsigned)(i - p);
        int v = (rel < (unsigned)NQ) ? labels[rel] : qlabels[i];
        out[1 + e] = (float)v;
    } else if (e == (long long)KD + KQ) {
        out[1 + e] = (float)((p + NQ) % KQ);
        g_correct = 0;
    }
}

// ---------------------------------------------------------------------------
// Kernel 2: bf16 mma.sync GEMM. CTA tile 128(M) x 256(N), BK=32, 8 warps,
// warp tile 64x64, double-buffered cp.async, padded smem (stride 40 halves).
// Chunk c: c<16 -> A_hi*B_hi; 16<=c<32 -> A_lo*B_hi; c>=32 -> A_hi*B_lo.
// ---------------------------------------------------------------------------
#define SA_STAGE 10240                 /* 128*40*2 bytes */
#define SB_STAGE 20480                 /* 256*40*2 bytes */
#define SB_BASE  (2 * SA_STAGE)
#define GEMM_SMEM (2 * SA_STAGE + 2 * SB_STAGE)   /* 61440 */

__global__ __launch_bounds__(256, 1) void gemm_tc_kernel()
{
    extern __shared__ char smem[];
    const uint32_t sbase = smem_u32(smem);
    const int tid  = threadIdx.x;
    const int lane = tid & 31;
    const int wid  = tid >> 5;
    const int wm   = wid & 1;          // 2 warps in M
    const int wn   = wid >> 1;         // 4 warps in N
    const int mBase = blockIdx.x * 128;
    const int nBase = blockIdx.y * 256;

    // ldmatrix base addresses (within stage 0)
    const uint32_t aAddr0 = sbase +
        (uint32_t)(((wm * 64) + (lane & 15)) * 80 + (lane >> 4) * 16);
    const uint32_t bAddr0 = sbase + SB_BASE +
        (uint32_t)(((wn * 64) + (lane & 7) + ((lane >> 4) & 1) * 8) * 80 + ((lane >> 3) & 1) * 16);

    auto issue_chunk = [&](int c, int s) {
        const int seg  = c >> 4;
        const int aCol = c * BK;
        const int bCol = ((seg == 2) ? 512 : 0) + (c & 15) * BK;
#pragma unroll
        for (int i = 0; i < 2; i++) {
            const int id = tid + i * 256;
            const int r = id >> 2, q = id & 3;
            uint32_t dst = sbase + s * SA_STAGE + (uint32_t)((r * 40 + q * 8) * 2);
            const void* src = g_af + (size_t)(mBase + r) * SPLITK + aCol + q * 8;
            CPASYNC(dst, src);
        }
#pragma unroll
        for (int i = 0; i < 4; i++) {
            const int id = tid + i * 256;
            const int r = id >> 2, q = id & 3;
            uint32_t dst = sbase + SB_BASE + s * SB_STAGE + (uint32_t)((r * 40 + q * 8) * 2);
            const void* src = g_bf + (size_t)(nBase + r) * BPK + bCol + q * 8;
            CPASYNC(dst, src);
        }
    };

    float c_[4][8][4];
#pragma unroll
    for (int i = 0; i < 4; i++)
#pragma unroll
        for (int j = 0; j < 8; j++)
#pragma unroll
            for (int t = 0; t < 4; t++) c_[i][j][t] = 0.f;

    issue_chunk(0, 0); CP_COMMIT();
    issue_chunk(1, 1); CP_COMMIT();

    for (int c = 0; c < NCHUNK; c++) {
        const int s = c & 1;
        CP_WAIT1();
        __syncthreads();

        const uint32_t aS = aAddr0 + s * SA_STAGE;
        const uint32_t bS = bAddr0 + s * SB_STAGE;
#pragma unroll
        for (int ks = 0; ks < 2; ks++) {
            uint32_t a[4][4];
#pragma unroll
            for (int mf = 0; mf < 4; mf++)
                LDSM_X4(a[mf][0], a[mf][1], a[mf][2], a[mf][3],
                        aS + mf * (16 * 80) + ks * 32);
            uint32_t b[4][4];
#pragma unroll
            for (int nf2 = 0; nf2 < 4; nf2++)
                LDSM_X4(b[nf2][0], b[nf2][1], b[nf2][2], b[nf2][3],
                        bS + nf2 * (16 * 80) + ks * 32);
#pragma unroll
            for (int mf = 0; mf < 4; mf++)
#pragma unroll
                for (int nf2 = 0; nf2 < 4; nf2++) {
                    MMA16816(c_[mf][nf2 * 2][0], c_[mf][nf2 * 2][1],
                             c_[mf][nf2 * 2][2], c_[mf][nf2 * 2][3],
                             a[mf][0], a[mf][1], a[mf][2], a[mf][3],
                             b[nf2][0], b[nf2][1]);
                    MMA16816(c_[mf][nf2 * 2 + 1][0], c_[mf][nf2 * 2 + 1][1],
                             c_[mf][nf2 * 2 + 1][2], c_[mf][nf2 * 2 + 1][3],
                             a[mf][0], a[mf][1], a[mf][2], a[mf][3],
                             b[nf2][2], b[nf2][3]);
                }
        }
        __syncthreads();
        if (c + 2 < NCHUNK) issue_chunk(c + 2, s);
        CP_COMMIT();
    }

    // Epilogue: direct float2 stores (32B-sector aligned per lane-quad)
    const int rBase = mBase + wm * 64 + (lane >> 2);
    const int cBase = nBase + wn * 64 + (lane & 3) * 2;
#pragma unroll
    for (int mf = 0; mf < 4; mf++) {
#pragma unroll
        for (int nf = 0; nf < 8; nf++) {
            float* p0 = g_sim + (size_t)(rBase + mf * 16) * KQ + cBase + nf * 8;
            float* p1 = p0 + (size_t)8 * KQ;
            *(float2*)p0 = make_float2(c_[mf][nf][0], c_[mf][nf][1]);
            *(float2*)p1 = make_float2(c_[mf][nf][2], c_[mf][nf][3]);
        }
    }
}

// ---------------------------------------------------------------------------
// Kernel 3: per-row top-200 (histogram threshold + exact sort) + class voting
// ---------------------------------------------------------------------------
__device__ __forceinline__ int sim_bin(float v)
{
    int b = (int)((v + 1.0f) * 2048.0f);
    return min(4095, max(0, b));
}

__global__ __launch_bounds__(256) void knn_select_kernel(const int* __restrict__ qlabels,
                                                         const int* __restrict__ labels)
{
    __shared__ unsigned hist[4096];
    __shared__ unsigned chunk[256];
    __shared__ float    cval[1024];
    __shared__ int      cidx[1024];
    __shared__ float    s_w[TOPK];
    __shared__ int      s_l[TOPK];
    __shared__ unsigned s_cnt;
    __shared__ int      s_tbin;

    const int tid = threadIdx.x;
    const int row = blockIdx.x;
    const float4* Sr4 = (const float4*)(g_sim + (size_t)row * KQ);

    for (int b = tid; b < 4096; b += 256) hist[b] = 0;
    if (tid == 0) s_cnt = 0;
    __syncthreads();

    for (int s = 0; s < 64; s++) {
        float4 v = Sr4[tid + s * 256];
        atomicAdd(&hist[sim_bin(v.x)], 1u);
        atomicAdd(&hist[sim_bin(v.y)], 1u);
        atomicAdd(&hist[sim_bin(v.z)], 1u);
        atomicAdd(&hist[sim_bin(v.w)], 1u);
    }
    __syncthreads();

    {
        unsigned cs = 0;
        const int b0 = tid * 16;
#pragma unroll
        for (int b = 0; b < 16; b++) cs += hist[b0 + b];
        chunk[tid] = cs;
    }
    __syncthreads();

    if (tid == 0) {
        unsigned cum = 0;
        int tb = 0;
        for (int t = 255; t >= 0; t--) {
            if (cum + chunk[t] >= (unsigned)TOPK) {
                for (int b = t * 16 + 15;; b--) {
                    if (cum + hist[b] >= (unsigned)TOPK) { tb = b; break; }
                    cum += hist[b];
                }
                break;
            }
            cum += chunk[t];
        }
        s_tbin = tb;
    }
    __syncthreads();
    const int tb = s_tbin;

    for (int s = 0; s < 64; s++) {
        const int base = tid + s * 256;
        float4 v = Sr4[base];
        float vv[4] = {v.x, v.y, v.z, v.w};
#pragma unroll
        for (int c = 0; c < 4; c++) {
            if (sim_bin(vv[c]) >= tb) {
                unsigned pos = atomicAdd(&s_cnt, 1u);
                if (pos < 1024u) { cval[pos] = vv[c]; cidx[pos] = base * 4 + c; }
            }
        }
    }
    __syncthreads();
    const int m = (int)min(s_cnt, 1024u);
    for (int i = tid; i < 1024; i += 256)
        if (i >= m) { cval[i] = -2.0f; cidx[i] = 0x7FFFFFFF; }
    __syncthreads();

    for (int k = 2; k <= 1024; k <<= 1) {
        for (int j = k >> 1; j > 0; j >>= 1) {
            for (int t = tid; t < 1024; t += 256) {
                const int p = t ^ j;
                if (p > t) {
                    float v1 = cval[t], v2 = cval[p];
                    int i1 = cidx[t], i2 = cidx[p];
                    bool firstGreater = (v1 > v2) || (v1 == v2 && i1 < i2);
                    bool up = ((t & k) == 0);
                    if (up != firstGreater) {
                        cval[t] = v2; cval[p] = v1;
                        cidx[t] = i2; cidx[p] = i1;
                    }
                }
            }
            __syncthreads();
        }
    }

    if (tid < TOPK) {
        s_w[tid] = expf(cval[tid] * (1.0f / 0.07f));
        s_l[tid] = qlabels[cidx[tid]];
    }
    __syncthreads();

    float best = -1.0f;
    int bc = 0;
#pragma unroll
    for (int rep = 0; rep < 4; rep++) {
        const int c = tid + rep * 256;
        if (c < NCLS) {
            float sc = 0.0f;
            for (int j = 0; j < TOPK; j++)
                if (s_l[j] == c) sc += s_w[j];
            if (sc > best) { best = sc; bc = c; }
        }
    }
    __syncthreads();
    cval[tid] = best; cidx[tid] = bc;
    __syncthreads();
    for (int off = 128; off > 0; off >>= 1) {
        if (tid < off) {
            float v2 = cval[tid + off]; int c2 = cidx[tid + off];
            if (v2 > cval[tid] || (v2 == cval[tid] && c2 < cidx[tid])) {
                cval[tid] = v2; cidx[tid] = c2;
            }
        }
        __syncthreads();
    }
    if (tid == 0 && cidx[0] == labels[row]) atomicAdd(&g_correct, 1);
}

__global__ void finalize_kernel(float* __restrict__ out)
{
    out[0] = (float)g_correct * (1.0f / 1024.0f);
}

// ---------------------------------------------------------------------------
extern "C" void kernel_launch(void* const* d_in, const int* in_sizes, int n_in,
                              void* d_out, int out_size)
{
    const float* feats   = (const float*)d_in[0];
    const float* qf      = (const float*)d_in[1];
    const int*   labels  = (const int*)d_in[2];
    const int*   qlabels = (const int*)d_in[3];
    const int*   qptr    = (const int*)d_in[4];
    float* out = (float*)d_out;

    cudaFuncSetAttribute(gemm_tc_kernel, cudaFuncAttributeMaxDynamicSharedMemorySize, GEMM_SMEM);

    conv_a_kernel<<<(NQ * DIM / 4) / 256, 256>>>(feats);
    conv_b_kernel<<<((size_t)KQ * DIM / 4) / 256, 256>>>(qf);

    const long long totalCopy = (long long)KD + KQ + 1;
    copy_update_kernel<<<(int)((totalCopy + 255) / 256), 256>>>(feats, qf, labels, qlabels, qptr, out);

    // grid: x = M tiles (8), y = N tiles (256). Consecutive bids share the B tile.
    gemm_tc_kernel<<<dim3(8, 256), 256, GEMM_SMEM>>>();
    knn_select_kernel<<<NQ, 256>>>(qlabels, labels);
    finalize_kernel<<<1, 1>>>(out);
}

// round 6
// speedup vs baseline: 1.7890x; 1.1629x over previous
#include <cuda_runtime.h>
#include <cuda_bf16.h>
#include <cstdint>

#define NQ   1024
#define DIM  512
#define KQ   65536
#define KD   (KQ * DIM)
#define NCLS 1000
#define TOPK 200
#define SPLITK 1536           /* 3 * DIM bf16-split K: [hi|lo|hi] */
#define BPK  1024             /* B' row width: [hi(512) | lo(512)] */
#define BK   32
#define NCHUNK 48             /* 1536 / 32, divisible by 3 */

// Device scratch (allocation-guard-legal)
__device__ __align__(256) float          g_sim[(size_t)NQ * KQ];     // 256 MB
__device__ __align__(256) __nv_bfloat16  g_bf[(size_t)KQ * BPK];     // 128 MB  [hi|lo]
__device__ __align__(256) __nv_bfloat16  g_af[(size_t)NQ * SPLITK];  //   3 MB  [hi|lo|hi]
__device__ int g_correct;

// ---------------------------------------------------------------------------
// PTX helpers (all base-sm_103 legal: cp.async / ldmatrix / mma.sync)
// ---------------------------------------------------------------------------
__device__ __forceinline__ uint32_t smem_u32(const void* p) {
    uint32_t a;
    asm("{ .reg .u64 t; cvta.to.shared.u64 t, %1; cvt.u32.u64 %0, t; }" : "=r"(a) : "l"(p));
    return a;
}
#define CPASYNC(dst, src) \
    asm volatile("cp.async.cg.shared.global [%0], [%1], 16;" :: "r"(dst), "l"(src))
#define CP_COMMIT()  asm volatile("cp.async.commit_group;" ::: "memory")
#define CP_WAIT1()   asm volatile("cp.async.wait_group 1;" ::: "memory")

#define LDSM_X4(r0, r1, r2, r3, addr) \
    asm volatile("ldmatrix.sync.aligned.m8n8.x4.shared.b16 {%0,%1,%2,%3}, [%4];" \
                 : "=r"(r0), "=r"(r1), "=r"(r2), "=r"(r3) : "r"(addr))

#define MMA16816(c0, c1, c2, c3, a0, a1, a2, a3, b0, b1) \
    asm volatile("mma.sync.aligned.m16n8k16.row.col.f32.bf16.bf16.f32 " \
                 "{%0,%1,%2,%3}, {%4,%5,%6,%7}, {%8,%9}, {%0,%1,%2,%3};" \
                 : "+f"(c0), "+f"(c1), "+f"(c2), "+f"(c3) \
                 : "r"(a0), "r"(a1), "r"(a2), "r"(a3), "r"(b0), "r"(b1))

// ---------------------------------------------------------------------------
// Kernel 0a/0b: bf16 hi/lo split conversion
// ---------------------------------------------------------------------------
__global__ void conv_b_kernel(const float* __restrict__ qf)
{
    size_t i4 = (size_t)blockIdx.x * 256 + threadIdx.x;
    float4 v = ((const float4*)qf)[i4];
    int row = (int)(i4 >> 7);
    int c4  = (int)(i4 & 127);
    float f[4] = {v.x, v.y, v.z, v.w};
    __nv_bfloat16 h[4], l[4];
#pragma unroll
    for (int j = 0; j < 4; j++) {
        h[j] = __float2bfloat16(f[j]);
        l[j] = __float2bfloat16(f[j] - __bfloat162float(h[j]));
    }
    __nv_bfloat16* base = g_bf + (size_t)row * BPK + c4 * 4;
    *(uint2*)base         = *(uint2*)h;
    *(uint2*)(base + 512) = *(uint2*)l;
}

__global__ void conv_a_kernel(const float* __restrict__ feats)
{
    size_t i4 = (size_t)blockIdx.x * 256 + threadIdx.x;
    float4 v = ((const float4*)feats)[i4];
    int row = (int)(i4 >> 7);
    int c4  = (int)(i4 & 127);
    float f[4] = {v.x, v.y, v.z, v.w};
    __nv_bfloat16 h[4], l[4];
#pragma unroll
    for (int j = 0; j < 4; j++) {
        h[j] = __float2bfloat16(f[j]);
        l[j] = __float2bfloat16(f[j] - __bfloat162float(h[j]));
    }
    __nv_bfloat16* base = g_af + (size_t)row * SPLITK + c4 * 4;
    *(uint2*)base          = *(uint2*)h;   // seg0: A_hi
    *(uint2*)(base + 512)  = *(uint2*)l;   // seg1: A_lo
    *(uint2*)(base + 1024) = *(uint2*)h;   // seg2: A_hi
}

// ---------------------------------------------------------------------------
// Kernel 1: circular-queue update copy + label copy + ptr + reset accumulator
// ---------------------------------------------------------------------------
__global__ void copy_update_kernel(const float* __restrict__ feats,
                                   const float* __restrict__ qf,
                                   const int*   __restrict__ labels,
                                   const int*   __restrict__ qlabels,
                                   const int*   __restrict__ qptr,
                                   float*       __restrict__ out)
{
    long long e = (long long)blockIdx.x * blockDim.x + threadIdx.x;
    const int p = qptr[0];
    if (e < (long long)KD) {
        int row = (int)(e >> 9);
        int col = (int)(e & 511);
        unsigned rel = (unsigned)(row - p);
        float v = (rel < (unsigned)NQ) ? feats[rel * DIM + col] : qf[e];
        out[1 + e] = v;
    } else if (e < (long long)KD + KQ) {
        int i = (int)(e - KD);
        unsigned rel = (unsigned)(i - p);
        int v = (rel < (unsigned)NQ) ? labels[rel] : qlabels[i];
        out[1 + e] = (float)v;
    } else if (e == (long long)KD + KQ) {
        out[1 + e] = (float)((p + NQ) % KQ);
        g_correct = 0;
    }
}

// ---------------------------------------------------------------------------
// Kernel 2: bf16 mma.sync GEMM. CTA tile 128(M) x 256(N), BK=32, 8 warps,
// warp tile 64x64, 3-stage cp.async pipeline, ONE barrier per chunk.
// Chunk c: c<16 -> A_hi*B_hi; 16<=c<32 -> A_lo*B_hi; c>=32 -> A_hi*B_lo.
// ---------------------------------------------------------------------------
#define SA_STAGE 10240                 /* 128*40*2 bytes */
#define SB_STAGE 20480                 /* 256*40*2 bytes */
#define SB_BASE  (3 * SA_STAGE)
#define GEMM_SMEM (3 * SA_STAGE + 3 * SB_STAGE)   /* 92160 */

__global__ __launch_bounds__(256, 1) void gemm_tc_kernel()
{
    extern __shared__ char smem[];
    const uint32_t sbase = smem_u32(smem);
    const int tid  = threadIdx.x;
    const int lane = tid & 31;
    const int wid  = tid >> 5;
    const int wm   = wid & 1;          // 2 warps in M
    const int wn   = wid >> 1;         // 4 warps in N
    const int mBase = blockIdx.x * 128;
    const int nBase = blockIdx.y * 256;

    // ldmatrix base addresses (within stage 0)
    const uint32_t aAddr0 = sbase +
        (uint32_t)(((wm * 64) + (lane & 15)) * 80 + (lane >> 4) * 16);
    const uint32_t bAddr0 = sbase + SB_BASE +
        (uint32_t)(((wn * 64) + (lane & 7) + ((lane >> 4) & 1) * 8) * 80 + ((lane >> 3) & 1) * 16);

    auto issue_chunk = [&](int c, int s) {
        const int seg  = c >> 4;
        const int aCol = c * BK;
        const int bCol = ((seg == 2) ? 512 : 0) + (c & 15) * BK;
#pragma unroll
        for (int i = 0; i < 2; i++) {
            const int id = tid + i * 256;
            const int r = id >> 2, q = id & 3;
            uint32_t dst = sbase + s * SA_STAGE + (uint32_t)((r * 40 + q * 8) * 2);
            const void* src = g_af + (size_t)(mBase + r) * SPLITK + aCol + q * 8;
            CPASYNC(dst, src);
        }
#pragma unroll
        for (int i = 0; i < 4; i++) {
            const int id = tid + i * 256;
            const int r = id >> 2, q = id & 3;
            uint32_t dst = sbase + SB_BASE + s * SB_STAGE + (uint32_t)((r * 40 + q * 8) * 2);
            const void* src = g_bf + (size_t)(nBase + r) * BPK + bCol + q * 8;
            CPASYNC(dst, src);
        }
    };

    float c_[4][8][4];
#pragma unroll
    for (int i = 0; i < 4; i++)
#pragma unroll
        for (int j = 0; j < 8; j++)
#pragma unroll
            for (int t = 0; t < 4; t++) c_[i][j][t] = 0.f;

    issue_chunk(0, 0); CP_COMMIT();
    issue_chunk(1, 1); CP_COMMIT();

    // One pipeline step: wait chunk c, barrier, issue chunk c+2 into stage s2,
    // then compute chunk c from stage s (fragments for both ks prefetched).
    auto step = [&](int c, int s, int s2) {
        CP_WAIT1();
        __syncthreads();
        if (c + 2 < NCHUNK) issue_chunk(c + 2, s2);
        CP_COMMIT();

        const uint32_t aS = aAddr0 + s * SA_STAGE;
        const uint32_t bS = bAddr0 + s * SB_STAGE;

        uint32_t a[2][4][4], b[2][4][4];
#pragma unroll
        for (int ks = 0; ks < 2; ks++) {
#pragma unroll
            for (int mf = 0; mf < 4; mf++)
                LDSM_X4(a[ks][mf][0], a[ks][mf][1], a[ks][mf][2], a[ks][mf][3],
                        aS + mf * (16 * 80) + ks * 32);
#pragma unroll
            for (int nf2 = 0; nf2 < 4; nf2++)
                LDSM_X4(b[ks][nf2][0], b[ks][nf2][1], b[ks][nf2][2], b[ks][nf2][3],
                        bS + nf2 * (16 * 80) + ks * 32);
        }
#pragma unroll
        for (int ks = 0; ks < 2; ks++)
#pragma unroll
            for (int mf = 0; mf < 4; mf++)
#pragma unroll
                for (int nf2 = 0; nf2 < 4; nf2++) {
                    MMA16816(c_[mf][nf2 * 2][0], c_[mf][nf2 * 2][1],
                             c_[mf][nf2 * 2][2], c_[mf][nf2 * 2][3],
                             a[ks][mf][0], a[ks][mf][1], a[ks][mf][2], a[ks][mf][3],
                             b[ks][nf2][0], b[ks][nf2][1]);
                    MMA16816(c_[mf][nf2 * 2 + 1][0], c_[mf][nf2 * 2 + 1][1],
                             c_[mf][nf2 * 2 + 1][2], c_[mf][nf2 * 2 + 1][3],
                             a[ks][mf][0], a[ks][mf][1], a[ks][mf][2], a[ks][mf][3],
                             b[ks][nf2][2], b[ks][nf2][3]);
                }
    };

#pragma unroll 1
    for (int cc = 0; cc < NCHUNK; cc += 3) {
        step(cc + 0, 0, 2);
        step(cc + 1, 1, 0);
        step(cc + 2, 2, 1);
    }

    // Epilogue: direct float2 stores (32B-sector aligned per lane-quad)
    const int rBase = mBase + wm * 64 + (lane >> 2);
    const int cBase = nBase + wn * 64 + (lane & 3) * 2;
#pragma unroll
    for (int mf = 0; mf < 4; mf++) {
#pragma unroll
        for (int nf = 0; nf < 8; nf++) {
            float* p0 = g_sim + (size_t)(rBase + mf * 16) * KQ + cBase + nf * 8;
            float* p1 = p0 + (size_t)8 * KQ;
            *(float2*)p0 = make_float2(c_[mf][nf][0], c_[mf][nf][1]);
            *(float2*)p1 = make_float2(c_[mf][nf][2], c_[mf][nf][3]);
        }
    }
}

// ---------------------------------------------------------------------------
// Kernel 3: per-row top-200 (histogram threshold + exact sort) + class voting
// ---------------------------------------------------------------------------
__device__ __forceinline__ int sim_bin(float v)
{
    int b = (int)((v + 1.0f) * 2048.0f);
    return min(4095, max(0, b));
}

__global__ __launch_bounds__(256) void knn_select_kernel(const int* __restrict__ qlabels,
                                                         const int* __restrict__ labels)
{
    __shared__ unsigned hist[4096];
    __shared__ unsigned chunk[256];
    __shared__ float    cval[1024];
    __shared__ int      cidx[1024];
    __shared__ float    s_w[TOPK];
    __shared__ int      s_l[TOPK];
    __shared__ unsigned s_cnt;
    __shared__ int      s_tbin;

    const int tid = threadIdx.x;
    const int row = blockIdx.x;
    const float4* Sr4 = (const float4*)(g_sim + (size_t)row * KQ);

    for (int b = tid; b < 4096; b += 256) hist[b] = 0;
    if (tid == 0) s_cnt = 0;
    __syncthreads();

    for (int s = 0; s < 64; s++) {
        float4 v = Sr4[tid + s * 256];
        atomicAdd(&hist[sim_bin(v.x)], 1u);
        atomicAdd(&hist[sim_bin(v.y)], 1u);
        atomicAdd(&hist[sim_bin(v.z)], 1u);
        atomicAdd(&hist[sim_bin(v.w)], 1u);
    }
    __syncthreads();

    {
        unsigned cs = 0;
        const int b0 = tid * 16;
#pragma unroll
        for (int b = 0; b < 16; b++) cs += hist[b0 + b];
        chunk[tid] = cs;
    }
    __syncthreads();

    if (tid == 0) {
        unsigned cum = 0;
        int tb = 0;
        for (int t = 255; t >= 0; t--) {
            if (cum + chunk[t] >= (unsigned)TOPK) {
                for (int b = t * 16 + 15;; b--) {
                    if (cum + hist[b] >= (unsigned)TOPK) { tb = b; break; }
                    cum += hist[b];
                }
                break;
            }
            cum += chunk[t];
        }
        s_tbin = tb;
    }
    __syncthreads();
    const int tb = s_tbin;

    for (int s = 0; s < 64; s++) {
        const int base = tid + s * 256;
        float4 v = Sr4[base];
        float vv[4] = {v.x, v.y, v.z, v.w};
#pragma unroll
        for (int c = 0; c < 4; c++) {
            if (sim_bin(vv[c]) >= tb) {
                unsigned pos = atomicAdd(&s_cnt, 1u);
                if (pos < 1024u) { cval[pos] = vv[c]; cidx[pos] = base * 4 + c; }
            }
        }
    }
    __syncthreads();
    const int m = (int)min(s_cnt, 1024u);
    for (int i = tid; i < 1024; i += 256)
        if (i >= m) { cval[i] = -2.0f; cidx[i] = 0x7FFFFFFF; }
    __syncthreads();

    for (int k = 2; k <= 1024; k <<= 1) {
        for (int j = k >> 1; j > 0; j >>= 1) {
            for (int t = tid; t < 1024; t += 256) {
                const int p = t ^ j;
                if (p > t) {
                    float v1 = cval[t], v2 = cval[p];
                    int i1 = cidx[t], i2 = cidx[p];
                    bool firstGreater = (v1 > v2) || (v1 == v2 && i1 < i2);
                    bool up = ((t & k) == 0);
                    if (up != firstGreater) {
                        cval[t] = v2; cval[p] = v1;
                        cidx[t] = i2; cidx[p] = i1;
                    }
                }
            }
            __syncthreads();
        }
    }

    if (tid < TOPK) {
        s_w[tid] = expf(cval[tid] * (1.0f / 0.07f));
        s_l[tid] = qlabels[cidx[tid]];
    }
    __syncthreads();

    float best = -1.0f;
    int bc = 0;
#pragma unroll
    for (int rep = 0; rep < 4; rep++) {
        const int c = tid + rep * 256;
        if (c < NCLS) {
            float sc = 0.0f;
            for (int j = 0; j < TOPK; j++)
                if (s_l[j] == c) sc += s_w[j];
            if (sc > best) { best = sc; bc = c; }
        }
    }
    __syncthreads();
    cval[tid] = best; cidx[tid] = bc;
    __syncthreads();
    for (int off = 128; off > 0; off >>= 1) {
        if (tid < off) {
            float v2 = cval[tid + off]; int c2 = cidx[tid + off];
            if (v2 > cval[tid] || (v2 == cval[tid] && c2 < cidx[tid])) {
                cval[tid] = v2; cidx[tid] = c2;
            }
        }
        __syncthreads();
    }
    if (tid == 0 && cidx[0] == labels[row]) atomicAdd(&g_correct, 1);
}

__global__ void finalize_kernel(float* __restrict__ out)
{
    out[0] = (float)g_correct * (1.0f / 1024.0f);
}

// ---------------------------------------------------------------------------
extern "C" void kernel_launch(void* const* d_in, const int* in_sizes, int n_in,
                              void* d_out, int out_size)
{
    const float* feats   = (const float*)d_in[0];
    const float* qf      = (const float*)d_in[1];
    const int*   labels  = (const int*)d_in[2];
    const int*   qlabels = (const int*)d_in[3];
    const int*   qptr    = (const int*)d_in[4];
    float* out = (float*)d_out;

    cudaFuncSetAttribute(gemm_tc_kernel, cudaFuncAttributeMaxDynamicSharedMemorySize, GEMM_SMEM);

    conv_a_kernel<<<(NQ * DIM / 4) / 256, 256>>>(feats);
    conv_b_kernel<<<((size_t)KQ * DIM / 4) / 256, 256>>>(qf);

    const long long totalCopy = (long long)KD + KQ + 1;
    copy_update_kernel<<<(int)((totalCopy + 255) / 256), 256>>>(feats, qf, labels, qlabels, qptr, out);

    // grid: x = M tiles (8), y = N tiles (256). Consecutive bids share the B tile.
    gemm_tc_kernel<<<dim3(8, 256), 256, GEMM_SMEM>>>();
    knn_select_kernel<<<NQ, 256>>>(qlabels, labels);
    finalize_kernel<<<1, 1>>>(out);
}

// round 8
// speedup vs baseline: 2.1909x; 1.2246x over previous
#include <cuda_runtime.h>
#include <cuda_bf16.h>
#include <cstdint>

#define NQ   1024
#define DIM  512
#define KQ   65536
#define KD   (KQ * DIM)
#define NCLS 1000
#define TOPK 200
#define SPLITK 1536           /* 3 * DIM bf16-split K: [hi|lo|hi] */
#define BPK  1024             /* B' row width: [hi(512) | lo(512)] */
#define BK   32
#define NCHUNK 48             /* 1536 / 32, divisible by 3 */

// Device scratch (allocation-guard-legal)
__device__ __align__(256) float          g_sim[(size_t)NQ * KQ];     // 256 MB
__device__ __align__(256) __nv_bfloat16  g_bf[(size_t)KQ * BPK];     // 128 MB  [hi|lo]
__device__ __align__(256) __nv_bfloat16  g_af[(size_t)NQ * SPLITK];  //   3 MB  [hi|lo|hi]
__device__ int g_correct;

// ---------------------------------------------------------------------------
// PTX helpers (all base-sm_103 legal: cp.async / ldmatrix / mma.sync)
// ---------------------------------------------------------------------------
__device__ __forceinline__ uint32_t smem_u32(const void* p) {
    uint32_t a;
    asm("{ .reg .u64 t; cvta.to.shared.u64 t, %1; cvt.u32.u64 %0, t; }" : "=r"(a) : "l"(p));
    return a;
}
#define CPASYNC(dst, src) \
    asm volatile("cp.async.cg.shared.global [%0], [%1], 16;" :: "r"(dst), "l"(src))
#define CP_COMMIT()  asm volatile("cp.async.commit_group;" ::: "memory")
#define CP_WAIT1()   asm volatile("cp.async.wait_group 1;" ::: "memory")

#define LDSM_X4(r0, r1, r2, r3, addr) \
    asm volatile("ldmatrix.sync.aligned.m8n8.x4.shared.b16 {%0,%1,%2,%3}, [%4];" \
                 : "=r"(r0), "=r"(r1), "=r"(r2), "=r"(r3) : "r"(addr))

#define MMA16816(c0, c1, c2, c3, a0, a1, a2, a3, b0, b1) \
    asm volatile("mma.sync.aligned.m16n8k16.row.col.f32.bf16.bf16.f32 " \
                 "{%0,%1,%2,%3}, {%4,%5,%6,%7}, {%8,%9}, {%0,%1,%2,%3};" \
                 : "+f"(c0), "+f"(c1), "+f"(c2), "+f"(c3) \
                 : "r"(a0), "r"(a1), "r"(a2), "r"(a3), "r"(b0), "r"(b1))

// ---------------------------------------------------------------------------
// Kernel 0: A-side bf16 hi/lo split
// ---------------------------------------------------------------------------
__global__ void conv_a_kernel(const float* __restrict__ feats)
{
    size_t i4 = (size_t)blockIdx.x * 256 + threadIdx.x;
    float4 v = ((const float4*)feats)[i4];
    int row = (int)(i4 >> 7);
    int c4  = (int)(i4 & 127);
    float f[4] = {v.x, v.y, v.z, v.w};
    __nv_bfloat16 h[4], l[4];
#pragma unroll
    for (int j = 0; j < 4; j++) {
        h[j] = __float2bfloat16(f[j]);
        l[j] = __float2bfloat16(f[j] - __bfloat162float(h[j]));
    }
    __nv_bfloat16* base = g_af + (size_t)row * SPLITK + c4 * 4;
    *(uint2*)base          = *(uint2*)h;   // seg0: A_hi
    *(uint2*)(base + 512)  = *(uint2*)l;   // seg1: A_lo
    *(uint2*)(base + 1024) = *(uint2*)h;   // seg2: A_hi
}

// ---------------------------------------------------------------------------
// Kernel 1 (fused): circular-queue update copy + B-side bf16 split + labels +
// ptr + accumulator reset. Saves one full 256 MB read of qf.
// Feature region handled at float4 granularity.
// ---------------------------------------------------------------------------
#define NF4 (KD / 4)          /* 8388608 float4 over the feature region */

__global__ void copy_conv_b_kernel(const float* __restrict__ feats,
                                   const float* __restrict__ qf,
                                   const int*   __restrict__ labels,
                                   const int*   __restrict__ qlabels,
                                   const int*   __restrict__ qptr,
                                   float*       __restrict__ out)
{
    long long idx = (long long)blockIdx.x * blockDim.x + threadIdx.x;
    const int p = qptr[0];
    if (idx < (long long)NF4) {
        float4 v = ((const float4*)qf)[idx];
        int row = (int)(idx >> 7);
        int c4  = (int)(idx & 127);
        // bf16 split of ORIGINAL queue rows (sim uses pre-update queue)
        float f[4] = {v.x, v.y, v.z, v.w};
        __nv_bfloat16 h[4], l[4];
#pragma unroll
        for (int j = 0; j < 4; j++) {
            h[j] = __float2bfloat16(f[j]);
            l[j] = __float2bfloat16(f[j] - __bfloat162float(h[j]));
        }
        __nv_bfloat16* bbase = g_bf + (size_t)row * BPK + c4 * 4;
        *(uint2*)bbase         = *(uint2*)h;
        *(uint2*)(bbase + 512) = *(uint2*)l;
        // queue update for out (out+1 is only 4B-aligned: scalar stores)
        unsigned rel = (unsigned)(row - p);
        float4 vo = (rel < (unsigned)NQ) ? ((const float4*)feats)[rel * 128 + c4] : v;
        float* o = out + 1 + idx * 4;
        o[0] = vo.x; o[1] = vo.y; o[2] = vo.z; o[3] = vo.w;
    } else if (idx < (long long)NF4 + KQ) {
        int i = (int)(idx - NF4);
        unsigned rel = (unsigned)(i - p);
        int v = (rel < (unsigned)NQ) ? labels[rel] : qlabels[i];
        out[1 + (long long)KD + i] = (float)v;
    } else if (idx == (long long)NF4 + KQ) {
        out[1 + (long long)KD + KQ] = (float)((p + NQ) % KQ);
        g_correct = 0;
    }
}

// ---------------------------------------------------------------------------
// Kernel 2: bf16 mma.sync GEMM. CTA tile 128(M) x 128(N), BK=32, 8 warps,
// warp tile 32x64 (4M x 2N warp grid), 3-stage cp.async pipeline, 2 CTAs/SM.
// Chunk c: c<16 -> A_hi*B_hi; 16<=c<32 -> A_lo*B_hi; c>=32 -> A_hi*B_lo.
// ---------------------------------------------------------------------------
#define SA_STAGE 10240                 /* 128*40*2 bytes */
#define SB_STAGE 10240                 /* 128*40*2 bytes */
#define SB_BASE  (3 * SA_STAGE)
#define GEMM_SMEM (3 * SA_STAGE + 3 * SB_STAGE)   /* 61440 */

__global__ __launch_bounds__(256, 2) void gemm_tc_kernel()
{
    extern __shared__ char smem[];
    const uint32_t sbase = smem_u32(smem);
    const int tid  = threadIdx.x;
    const int lane = tid & 31;
    const int wid  = tid >> 5;
    const int wm   = wid & 3;          // 4 warps in M
    const int wn   = wid >> 2;         // 2 warps in N
    const int mBase = blockIdx.x * 128;
    const int nBase = blockIdx.y * 128;

    // ldmatrix base addresses (within stage 0)
    const uint32_t aAddr0 = sbase +
        (uint32_t)(((wm * 32) + (lane & 15)) * 80 + (lane >> 4) * 16);
    const uint32_t bAddr0 = sbase + SB_BASE +
        (uint32_t)(((wn * 64) + (lane & 7) + ((lane >> 4) & 1) * 8) * 80 + ((lane >> 3) & 1) * 16);

    auto issue_chunk = [&](int c, int s) {
        const int seg  = c >> 4;
        const int aCol = c * BK;
        const int bCol = ((seg == 2) ? 512 : 0) + (c & 15) * BK;
#pragma unroll
        for (int i = 0; i < 2; i++) {
            const int id = tid + i * 256;
            const int r = id >> 2, q = id & 3;
            uint32_t dstA = sbase + s * SA_STAGE + (uint32_t)((r * 40 + q * 8) * 2);
            const void* srcA = g_af + (size_t)(mBase + r) * SPLITK + aCol + q * 8;
            CPASYNC(dstA, srcA);
            uint32_t dstB = sbase + SB_BASE + s * SB_STAGE + (uint32_t)((r * 40 + q * 8) * 2);
            const void* srcB = g_bf + (size_t)(nBase + r) * BPK + bCol + q * 8;
            CPASYNC(dstB, srcB);
        }
    };

    float c_[2][8][4];
#pragma unroll
    for (int i = 0; i < 2; i++)
#pragma unroll
        for (int j = 0; j < 8; j++)
#pragma unroll
            for (int t = 0; t < 4; t++) c_[i][j][t] = 0.f;

    issue_chunk(0, 0); CP_COMMIT();
    issue_chunk(1, 1); CP_COMMIT();

    auto step = [&](int c, int s, int s2) {
        CP_WAIT1();
        __syncthreads();
        if (c + 2 < NCHUNK) issue_chunk(c + 2, s2);
        CP_COMMIT();

        const uint32_t aS = aAddr0 + s * SA_STAGE;
        const uint32_t bS = bAddr0 + s * SB_STAGE;

        uint32_t a[2][2][4], b[2][4][4];
#pragma unroll
        for (int ks = 0; ks < 2; ks++) {
#pragma unroll
            for (int mf = 0; mf < 2; mf++)
                LDSM_X4(a[ks][mf][0], a[ks][mf][1], a[ks][mf][2], a[ks][mf][3],
                        aS + mf * (16 * 80) + ks * 32);
#pragma unroll
            for (int nf2 = 0; nf2 < 4; nf2++)
                LDSM_X4(b[ks][nf2][0], b[ks][nf2][1], b[ks][nf2][2], b[ks][nf2][3],
                        bS + nf2 * (16 * 80) + ks * 32);
        }
#pragma unroll
        for (int ks = 0; ks < 2; ks++)
#pragma unroll
            for (int mf = 0; mf < 2; mf++)
#pragma unroll
                for (int nf2 = 0; nf2 < 4; nf2++) {
                    MMA16816(c_[mf][nf2 * 2][0], c_[mf][nf2 * 2][1],
                             c_[mf][nf2 * 2][2], c_[mf][nf2 * 2][3],
                             a[ks][mf][0], a[ks][mf][1], a[ks][mf][2], a[ks][mf][3],
                             b[ks][nf2][0], b[ks][nf2][1]);
                    MMA16816(c_[mf][nf2 * 2 + 1][0], c_[mf][nf2 * 2 + 1][1],
                             c_[mf][nf2 * 2 + 1][2], c_[mf][nf2 * 2 + 1][3],
                             a[ks][mf][0], a[ks][mf][1], a[ks][mf][2], a[ks][mf][3],
                             b[ks][nf2][2], b[ks][nf2][3]);
                }
    };

#pragma unroll 1
    for (int cc = 0; cc < NCHUNK; cc += 3) {
        step(cc + 0, 0, 2);
        step(cc + 1, 1, 0);
        step(cc + 2, 2, 1);
    }

    // Epilogue: direct float2 stores
    const int rBase = mBase + wm * 32 + (lane >> 2);
    const int cBase = nBase + wn * 64 + (lane & 3) * 2;
#pragma unroll
    for (int mf = 0; mf < 2; mf++) {
#pragma unroll
        for (int nf = 0; nf < 8; nf++) {
            float* p0 = g_sim + (size_t)(rBase + mf * 16) * KQ + cBase + nf * 8;
            float* p1 = p0 + (size_t)8 * KQ;
            *(float2*)p0 = make_float2(c_[mf][nf][0], c_[mf][nf][1]);
            *(float2*)p1 = make_float2(c_[mf][nf][2], c_[mf][nf][3]);
        }
    }
}

// ---------------------------------------------------------------------------
// Kernel 3: per-row top-200 (histogram threshold + 512-sort) + atomic voting
// ---------------------------------------------------------------------------
__device__ __forceinline__ int sim_bin(float v)
{
    int b = (int)((v + 1.0f) * 2048.0f);
    return min(4095, max(0, b));
}

#define CBUF 512

__global__ __launch_bounds__(256) void knn_select_kernel(const int* __restrict__ qlabels,
                                                         const int* __restrict__ labels)
{
    __shared__ unsigned hist[4096];
    __shared__ unsigned chunk[256];
    __shared__ float    cval[CBUF];
    __shared__ int      cidx[CBUF];
    __shared__ float    score[NCLS];
    __shared__ unsigned s_cnt;
    __shared__ int      s_tbin;

    const int tid = threadIdx.x;
    const int row = blockIdx.x;
    const float4* Sr4 = (const float4*)(g_sim + (size_t)row * KQ);

    for (int b = tid; b < 4096; b += 256) hist[b] = 0;
    for (int i = tid; i < NCLS; i += 256) score[i] = 0.0f;
    if (tid == 0) s_cnt = 0;
    __syncthreads();

    // Pass 1: histogram over [-1, 1] with 4096 linear bins
    for (int s = 0; s < 64; s++) {
        float4 v = Sr4[tid + s * 256];
        atomicAdd(&hist[sim_bin(v.x)], 1u);
        atomicAdd(&hist[sim_bin(v.y)], 1u);
        atomicAdd(&hist[sim_bin(v.z)], 1u);
        atomicAdd(&hist[sim_bin(v.w)], 1u);
    }
    __syncthreads();

    {
        unsigned cs = 0;
        const int b0 = tid * 16;
#pragma unroll
        for (int b = 0; b < 16; b++) cs += hist[b0 + b];
        chunk[tid] = cs;
    }
    __syncthreads();

    if (tid == 0) {
        unsigned cum = 0;
        int tb = 0;
        for (int t = 255; t >= 0; t--) {
            if (cum + chunk[t] >= (unsigned)TOPK) {
                for (int b = t * 16 + 15;; b--) {
                    if (cum + hist[b] >= (unsigned)TOPK) { tb = b; break; }
                    cum += hist[b];
                }
                break;
            }
            cum += chunk[t];
        }
        s_tbin = tb;
    }
    __syncthreads();
    const int tb = s_tbin;

    // Pass 2: gather all candidates with bin >= tb (count typically ~205)
    for (int s = 0; s < 64; s++) {
        const int base = tid + s * 256;
        float4 v = Sr4[base];
        float vv[4] = {v.x, v.y, v.z, v.w};
#pragma unroll
        for (int c = 0; c < 4; c++) {
            if (sim_bin(vv[c]) >= tb) {
                unsigned pos = atomicAdd(&s_cnt, 1u);
                if (pos < (unsigned)CBUF) { cval[pos] = vv[c]; cidx[pos] = base * 4 + c; }
            }
        }
    }
    __syncthreads();
    const int m = (int)min(s_cnt, (unsigned)CBUF);
    for (int i = tid; i < CBUF; i += 256)
        if (i >= m) { cval[i] = -2.0f; cidx[i] = 0x7FFFFFFF; }
    __syncthreads();

    // Bitonic sort 512: descending by value, ascending by index on ties
    for (int k = 2; k <= CBUF; k <<= 1) {
        for (int j = k >> 1; j > 0; j >>= 1) {
            for (int t = tid; t < CBUF; t += 256) {
                const int p = t ^ j;
                if (p > t) {
                    float v1 = cval[t], v2 = cval[p];
                    int i1 = cidx[t], i2 = cidx[p];
                    bool firstGreater = (v1 > v2) || (v1 == v2 && i1 < i2);
                    bool up = ((t & k) == 0);
                    if (up != firstGreater) {
                        cval[t] = v2; cval[p] = v1;
                        cidx[t] = i2; cidx[p] = i1;
                    }
                }
            }
            __syncthreads();
        }
    }

    // Vote: exact top-200 weights scattered into per-class scores
    if (tid < TOPK) {
        float w = expf(cval[tid] * (1.0f / 0.07f));
        atomicAdd(&score[qlabels[cidx[tid]]], w);
    }
    __syncthreads();

    // Argmax over classes (lowest class index on ties)
    float best = -1.0f;
    int bc = 0;
#pragma unroll
    for (int rep = 0; rep < 4; rep++) {
        const int c = tid + rep * 256;
        if (c < NCLS) {
            float sc = score[c];
            if (sc > best) { best = sc; bc = c; }
        }
    }
    __syncthreads();
    cval[tid] = best; cidx[tid] = bc;
    __syncthreads();
    for (int off = 128; off > 0; off >>= 1) {
        if (tid < off) {
            float v2 = cval[tid + off]; int c2 = cidx[tid + off];
            if (v2 > cval[tid] || (v2 == cval[tid] && c2 < cidx[tid])) {
                cval[tid] = v2; cidx[tid] = c2;
            }
        }
        __syncthreads();
    }
    if (tid == 0 && cidx[0] == labels[row]) atomicAdd(&g_correct, 1);
}

__global__ void finalize_kernel(float* __restrict__ out)
{
    out[0] = (float)g_correct * (1.0f / 1024.0f);
}

// ---------------------------------------------------------------------------
extern "C" void kernel_launch(void* const* d_in, const int* in_sizes, int n_in,
                              void* d_out, int out_size)
{
    const float* feats   = (const float*)d_in[0];
    const float* qf      = (const float*)d_in[1];
    const int*   labels  = (const int*)d_in[2];
    const int*   qlabels = (const int*)d_in[3];
    const int*   qptr    = (const int*)d_in[4];
    float* out = (float*)d_out;

    cudaFuncSetAttribute(gemm_tc_kernel, cudaFuncAttributeMaxDynamicSharedMemorySize, GEMM_SMEM);

    conv_a_kernel<<<(NQ * DIM / 4) / 256, 256>>>(feats);

    const long long total = (long long)NF4 + KQ + 1;
    copy_conv_b_kernel<<<(int)((total + 255) / 256), 256>>>(feats, qf, labels, qlabels, qptr, out);

    // grid: x = M tiles (8), y = N tiles (512). Consecutive bids share the B tile.
    gemm_tc_kernel<<<dim3(8, 512), 256, GEMM_SMEM>>>();
    knn_select_kernel<<<NQ, 256>>>(qlabels, labels);
    finalize_kernel<<<1, 1>>>(out);
}